// round 5
// baseline (speedup 1.0000x reference)
#include <cuda_runtime.h>
#include <cuda_bf16.h>
#include <cstdint>

#define DIMK   4096
#define NEXP   64
#define BTOK   16384
#define MTILE  128
#define KB     64
#define NCHUNK (DIMK / KB)
#define NTHR   256
#define NSTG   4
#define STG_SZ 49152                 // 32KB A(fp32) + 16KB B(bf16 x2 splits)
#define BIAS_OFF 196608
#define CNT_OFF  196864
#define LIST_OFF 196880
#define SMEM_BYTES 197632
#define DELTA  1e-3f

// pre-split, pre-swizzled w tiles: [chunk][split][64e*64k bf16]
static __device__ __align__(16) unsigned short g_ws[NCHUNK][2][4096];

__device__ __forceinline__ unsigned smem_u32(const void* p) {
    return (unsigned)__cvta_generic_to_shared(p);
}
__device__ __forceinline__ void cpa16(unsigned dst, const void* src) {
    asm volatile("cp.async.cg.shared.global [%0], [%1], 16;" :: "r"(dst), "l"(src));
}
__device__ __forceinline__ unsigned packbf(float hi, float lo) {
    unsigned r;
    asm("cvt.rn.bf16x2.f32 %0, %1, %2;" : "=r"(r) : "f"(hi), "f"(lo));
    return r;
}
__device__ __forceinline__ unsigned prmt_hi(unsigned a, unsigned b) {
    unsigned r;
    asm("prmt.b32 %0, %1, %2, 0x7632;" : "=r"(r) : "r"(a), "r"(b));
    return r;
}
__device__ __forceinline__ void ldsm4(unsigned* r, unsigned a) {
    asm volatile("ldmatrix.sync.aligned.m8n8.x4.shared.b16 {%0,%1,%2,%3}, [%4];"
                 : "=r"(r[0]), "=r"(r[1]), "=r"(r[2]), "=r"(r[3]) : "r"(a));
}
#define MMA(d, a, b0v, b1v)                                                    \
    asm volatile(                                                              \
        "mma.sync.aligned.m16n8k16.row.col.f32.bf16.bf16.f32 "                 \
        "{%0,%1,%2,%3},{%4,%5,%6,%7},{%8,%9},{%0,%1,%2,%3};"                   \
        : "+f"((d)[0]), "+f"((d)[1]), "+f"((d)[2]), "+f"((d)[3])               \
        : "r"((a)[0]), "r"((a)[1]), "r"((a)[2]), "r"((a)[3]),                  \
          "r"(b0v), "r"(b1v))

__global__ void wsplit_kernel(const float* __restrict__ w) {
    const int idx = blockIdx.x * 256 + threadIdx.x;
    const int e = idx >> 12, k = idx & 4095;
    const float x = w[idx];
    const unsigned short b0 = __bfloat16_as_ushort(__float2bfloat16(x));
    const float r = x - __uint_as_float((unsigned)b0 << 16);
    const unsigned short b1 = __bfloat16_as_ushort(__float2bfloat16(r));
    const int c = k >> 6, kk = k & 63;
    const unsigned off = ((unsigned)e << 7) + (((unsigned)kk * 2) ^ ((e & 7) << 4));
    g_ws[c][0][off >> 1] = b0;
    g_ws[c][1][off >> 1] = b1;
}

__global__ void __launch_bounds__(NTHR, 1)
mome_gate_mma(const float* __restrict__ h,
              const float* __restrict__ w,
              const float* __restrict__ bias,
              float* __restrict__ out)
{
    extern __shared__ char smc[];
    const unsigned smb = smem_u32(smc);
    const int tid  = threadIdx.x;
    const int lane = tid & 31;
    const int wid  = tid >> 5;
    const int wr   = wid >> 1;
    const int we   = wid & 1;
    const size_t rowBase = (size_t)blockIdx.x * MTILE;

    if (tid == 0) *(int*)(smc + CNT_OFF) = 0;
    if (tid < NEXP) ((float*)(smc + BIAS_OFF))[tid] = bias[tid];

    // producer mapping: 16B units of fp32 A rows, XOR swizzle in 8B units
    const int  prow = tid >> 4;                       // +16*i
    const int  pu16 = tid & 15;
    const unsigned pxor = ((unsigned)(prow & 7)) << 2;
    const float* hsrc0 = h + (rowBase + prow) * DIMK + pu16 * 4;
    const unsigned adst0 = (unsigned)(prow * 256 + (((2 * pu16) ^ pxor) << 3));

    // B ldmatrix geometry (proven in round 4)
    const int mrow  = (lane & 7) + ((lane >> 3) & 1) * 8;
    const unsigned klane = ((unsigned)(lane >> 4)) * 16;
    const unsigned xorv  = ((unsigned)(lane & 7)) << 4;
    const unsigned browoff = (unsigned)(we * 32 + mrow) * 128;

    // A fp32-fragment geometry
    const int rowA = wr * 32 + (lane >> 2);
    const unsigned xorA = ((unsigned)(lane >> 2)) << 2;

    float acc[2][4][4];
#pragma unroll
    for (int m = 0; m < 2; m++)
#pragma unroll
        for (int n = 0; n < 4; n++)
#pragma unroll
            for (int q = 0; q < 4; q++) acc[m][n][q] = 0.f;

    auto loadAB = [&](int c, int stage) {
        const unsigned sb = smb + stage * STG_SZ;
        const float* hs = hsrc0 + c * KB;
#pragma unroll
        for (int i = 0; i < 8; i++)
            cpa16(sb + adst0 + i * 16 * 256, hs + (size_t)i * 16 * DIMK);
        const char* bsrc = (const char*)g_ws[c];
#pragma unroll
        for (int j = 0; j < 4; j++)
            cpa16(sb + 32768 + j * 4096 + tid * 16, bsrc + j * 4096 + tid * 16);
        asm volatile("cp.async.commit_group;" ::: "memory");
    };

    auto compute = [&](int stage) {
        const char* Ab = smc + stage * STG_SZ;
        const unsigned Bb = smb + stage * STG_SZ + 32768 + browoff;
#pragma unroll
        for (int kb = 0; kb < 4; kb++) {
            const unsigned ko = ((unsigned)kb * 32 + klane) ^ xorv;
            unsigned b0s0[4], b1s0[4], b0s1[4], b1s1[4];
            ldsm4(b0s0, Bb + ko);
            ldsm4(b1s0, Bb + 2048 + ko);
            ldsm4(b0s1, Bb + 8192 + ko);
            ldsm4(b1s1, Bb + 8192 + 2048 + ko);

            unsigned A0[2][4], A1[2][4];
#pragma unroll
            for (int m = 0; m < 2; m++)
#pragma unroll
                for (int q = 0; q < 4; q++) {
                    const int row = rowA + m * 16 + (q & 1) * 8;
                    const unsigned u = (unsigned)(lane & 3) + (unsigned)((q >> 1) * 4)
                                     + (unsigned)(kb * 8);
                    const float2 v = *(const float2*)(Ab + row * 256 + ((u ^ xorA) << 3));
                    const unsigned hx = __float_as_uint(v.x);
                    const unsigned hy = __float_as_uint(v.y);
                    A0[m][q] = prmt_hi(hx, hy);
                    const float rx = v.x - __uint_as_float(hx & 0xffff0000u);
                    const float ry = v.y - __uint_as_float(hy & 0xffff0000u);
                    A1[m][q] = packbf(ry, rx);
                }

#pragma unroll
            for (int m = 0; m < 2; m++) {
                MMA(acc[m][0], A0[m], b0s0[0], b0s0[2]);
                MMA(acc[m][1], A0[m], b0s0[1], b0s0[3]);
                MMA(acc[m][2], A0[m], b1s0[0], b1s0[2]);
                MMA(acc[m][3], A0[m], b1s0[1], b1s0[3]);
            }
#pragma unroll
            for (int m = 0; m < 2; m++) {
                MMA(acc[m][0], A0[m], b0s1[0], b0s1[2]);
                MMA(acc[m][1], A0[m], b0s1[1], b0s1[3]);
                MMA(acc[m][2], A0[m], b1s1[0], b1s1[2]);
                MMA(acc[m][3], A0[m], b1s1[1], b1s1[3]);
            }
#pragma unroll
            for (int m = 0; m < 2; m++) {
                MMA(acc[m][0], A1[m], b0s0[0], b0s0[2]);
                MMA(acc[m][1], A1[m], b0s0[1], b0s0[3]);
                MMA(acc[m][2], A1[m], b1s0[0], b1s0[2]);
                MMA(acc[m][3], A1[m], b1s0[1], b1s0[3]);
            }
        }
    };

    // prologue: fill 3 stages
    loadAB(0, 0);
    loadAB(1, 1);
    loadAB(2, 2);

    for (int c = 0; c < NCHUNK; c++) {
        asm volatile("cp.async.wait_group 2;" ::: "memory");
        __syncthreads();
        if (c + NSTG - 1 < NCHUNK) loadAB(c + NSTG - 1, (c + NSTG - 1) & (NSTG - 1));
        compute(c & (NSTG - 1));
    }
    asm volatile("cp.async.wait_group 0;" ::: "memory");
    __syncthreads();

    // ---- logits -> smem: Ls[128][68] ----
    float* Ls = (float*)smc;
    {
        const int rin = lane >> 2;
        const int cin = (lane & 3) * 2;
#pragma unroll
        for (int m = 0; m < 2; m++) {
            const int r0i = wr * 32 + m * 16 + rin;
#pragma unroll
            for (int j = 0; j < 4; j++) {
                const int n = we * 32 + j * 8 + cin;
                Ls[r0i * 68 + n]           = acc[m][j][0];
                Ls[r0i * 68 + n + 1]       = acc[m][j][1];
                Ls[(r0i + 8) * 68 + n]     = acc[m][j][2];
                Ls[(r0i + 8) * 68 + n + 1] = acc[m][j][3];
            }
        }
    }
    __syncthreads();

    // ---- per-row top-3 scan, flag near-ties ----
    const float* bias_s = (const float*)(smc + BIAS_OFF);
    if (tid < MTILE) {
        const float* lrow = &Ls[tid * 68];
        float v0 = -1e30f, v1 = -1e30f, v2 = -1e30f;
        int i0 = 0, i1 = 0;
#pragma unroll 8
        for (int e = 0; e < NEXP; e++) {
            const float v = lrow[e] + bias_s[e];
            if (v > v0)      { v2 = v1; v1 = v0; i1 = i0; v0 = v; i0 = e; }
            else if (v > v1) { v2 = v1; v1 = v; i1 = e; }
            else if (v > v2) { v2 = v; }
        }
        if ((v0 - v1 < DELTA) || (v1 - v2 < DELTA)) {
            const int slot = atomicAdd((int*)(smc + CNT_OFF), 1);
            ((int*)(smc + LIST_OFF))[slot] = tid;
        } else {
            const float t  = __expf(v1 - v0);
            const float w0 = 1.0f / (1.0f + t);
            const size_t g = rowBase + tid;
            out[2 * g]     = w0;
            out[2 * g + 1] = 1.0f - w0;
            float* oi = out + 2 * (size_t)BTOK;
            oi[2 * g]     = (float)i0;
            oi[2 * g + 1] = (float)i1;
        }
    }
    __syncthreads();

    // ---- exact fp32 rescue for flagged rows ----
    const int nf = *(const int*)(smc + CNT_OFF);
    float* P  = (float*)smc;
    float* Lr = (float*)(smc + 4096);
    for (int f = 0; f < nf; f++) {
        const int rrow = ((const int*)(smc + LIST_OFF))[f];
        const float* hr = h + (rowBase + rrow) * DIMK;
        const int e = tid & 63, q = tid >> 6;
        const float* wp = w + (size_t)e * DIMK + q * 1024;
        const float* hp = hr + q * 1024;
        float s = 0.f;
        for (int k = 0; k < 1024; k += 4) {
            const float4 hv = *(const float4*)(hp + k);
            const float4 wv = *(const float4*)(wp + k);
            s += hv.x * wv.x + hv.y * wv.y + hv.z * wv.z + hv.w * wv.w;
        }
        P[q * 64 + e] = s;
        __syncthreads();
        if (tid < NEXP)
            Lr[tid] = P[tid] + P[64 + tid] + P[128 + tid] + P[192 + tid] + bias_s[tid];
        __syncthreads();
        if (tid == 0) {
            float v0 = -1e30f, v1 = -1e30f;
            int i0 = 0, i1 = 0;
            for (int e2 = 0; e2 < NEXP; e2++) {
                const float v = Lr[e2];
                if (v > v0)      { v1 = v0; i1 = i0; v0 = v; i0 = e2; }
                else if (v > v1) { v1 = v; i1 = e2; }
            }
            const float t  = __expf(v1 - v0);
            const float w0 = 1.0f / (1.0f + t);
            const size_t g = rowBase + rrow;
            out[2 * g]     = w0;
            out[2 * g + 1] = 1.0f - w0;
            float* oi = out + 2 * (size_t)BTOK;
            oi[2 * g]     = (float)i0;
            oi[2 * g + 1] = (float)i1;
        }
        __syncthreads();
    }
}

extern "C" void kernel_launch(void* const* d_in, const int* in_sizes, int n_in,
                              void* d_out, int out_size)
{
    const float* h    = (const float*)d_in[0];
    const float* w    = (const float*)d_in[1];
    const float* bias = (const float*)d_in[2];
    float* out        = (float*)d_out;

    wsplit_kernel<<<(NEXP * DIMK) / 256, 256>>>(w);

    cudaFuncSetAttribute(mome_gate_mma,
                         cudaFuncAttributeMaxDynamicSharedMemorySize, SMEM_BYTES);
    mome_gate_mma<<<BTOK / MTILE, NTHR, SMEM_BYTES>>>(h, w, bias, out);
}

// round 6
// speedup vs baseline: 1.0174x; 1.0174x over previous
#include <cuda_runtime.h>
#include <cuda_bf16.h>
#include <cstdint>

#define DIMK   4096
#define NEXP   64
#define BTOK   16384
#define MTILE  128
#define KB     64
#define NCHUNK (DIMK / KB)
#define NTHR   512
#define NSTG   4
#define STG_SZ 49152                 // 32KB A(fp32) + 16KB B(bf16 x2 splits)
#define BIAS_OFF 196608
#define CNT_OFF  196864
#define LIST_OFF 196880
#define SMEM_BYTES 197632
#define DELTA  1e-3f

// pre-split, pre-swizzled w tiles: [chunk][split][64e*64k bf16]
static __device__ __align__(16) unsigned short g_ws[NCHUNK][2][4096];

__device__ __forceinline__ unsigned smem_u32(const void* p) {
    return (unsigned)__cvta_generic_to_shared(p);
}
__device__ __forceinline__ void cpa16(unsigned dst, const void* src) {
    asm volatile("cp.async.cg.shared.global [%0], [%1], 16;" :: "r"(dst), "l"(src));
}
__device__ __forceinline__ unsigned packbf(float hi, float lo) {
    unsigned r;
    asm("cvt.rn.bf16x2.f32 %0, %1, %2;" : "=r"(r) : "f"(hi), "f"(lo));
    return r;
}
__device__ __forceinline__ unsigned prmt_hi(unsigned a, unsigned b) {
    unsigned r;
    asm("prmt.b32 %0, %1, %2, 0x7632;" : "=r"(r) : "r"(a), "r"(b));
    return r;
}
__device__ __forceinline__ void ldsm4(unsigned* r, unsigned a) {
    asm volatile("ldmatrix.sync.aligned.m8n8.x4.shared.b16 {%0,%1,%2,%3}, [%4];"
                 : "=r"(r[0]), "=r"(r[1]), "=r"(r[2]), "=r"(r[3]) : "r"(a));
}
#define MMA(d, a, b0v, b1v)                                                    \
    asm volatile(                                                              \
        "mma.sync.aligned.m16n8k16.row.col.f32.bf16.bf16.f32 "                 \
        "{%0,%1,%2,%3},{%4,%5,%6,%7},{%8,%9},{%0,%1,%2,%3};"                   \
        : "+f"((d)[0]), "+f"((d)[1]), "+f"((d)[2]), "+f"((d)[3])               \
        : "r"((a)[0]), "r"((a)[1]), "r"((a)[2]), "r"((a)[3]),                  \
          "r"(b0v), "r"(b1v))

__global__ void wsplit_kernel(const float* __restrict__ w) {
    const int idx = blockIdx.x * 256 + threadIdx.x;
    const int e = idx >> 12, k = idx & 4095;
    const float x = w[idx];
    const unsigned short b0 = __bfloat16_as_ushort(__float2bfloat16(x));
    const float r = x - __uint_as_float((unsigned)b0 << 16);
    const unsigned short b1 = __bfloat16_as_ushort(__float2bfloat16(r));
    const int c = k >> 6, kk = k & 63;
    const unsigned off = ((unsigned)e << 7) + (((unsigned)kk * 2) ^ ((e & 7) << 4));
    g_ws[c][0][off >> 1] = b0;
    g_ws[c][1][off >> 1] = b1;
}

__global__ void __launch_bounds__(NTHR, 1)
mome_gate_mma(const float* __restrict__ h,
              const float* __restrict__ w,
              const float* __restrict__ bias,
              float* __restrict__ out)
{
    extern __shared__ char smc[];
    const unsigned smb = smem_u32(smc);
    const int tid  = threadIdx.x;
    const int lane = tid & 31;
    const int wid  = tid >> 5;       // 0..15
    const int wr   = wid >> 1;       // 0..7  -> rows wr*16 .. wr*16+15
    const int we   = wid & 1;        //       -> experts we*32 .. +31
    const size_t rowBase = (size_t)blockIdx.x * MTILE;

    if (tid == 0) *(int*)(smc + CNT_OFF) = 0;
    if (tid < NEXP) ((float*)(smc + BIAS_OFF))[tid] = bias[tid];

    // producer mapping: A chunk = 128 rows x 64 k fp32; 512 thr x 4 cpa16
    const int  prow = tid >> 4;                       // 0..31, +32*i
    const int  pu16 = tid & 15;
    const unsigned pxor = ((unsigned)(prow & 7)) << 2;
    const float* hsrc0 = h + (rowBase + prow) * DIMK + pu16 * 4;
    const unsigned adst0 = (unsigned)(prow * 256 + (((2 * pu16) ^ pxor) << 3));

    // B ldmatrix geometry (proven)
    const int mrow  = (lane & 7) + ((lane >> 3) & 1) * 8;
    const unsigned klane = ((unsigned)(lane >> 4)) * 16;
    const unsigned xorv  = ((unsigned)(lane & 7)) << 4;
    const unsigned browoff = (unsigned)(we * 32 + mrow) * 128;

    // A fp32-fragment geometry (16-row warp tile)
    const int rowA = wr * 16 + (lane >> 2);
    const unsigned xorA = ((unsigned)(lane >> 2)) << 2;

    float acc[4][4];
#pragma unroll
    for (int n = 0; n < 4; n++)
#pragma unroll
        for (int q = 0; q < 4; q++) acc[n][q] = 0.f;

    auto loadAB = [&](int c, int stage) {
        const unsigned sb = smb + stage * STG_SZ;
        const float* hs = hsrc0 + c * KB;
#pragma unroll
        for (int i = 0; i < 4; i++)
            cpa16(sb + adst0 + i * 32 * 256, hs + (size_t)i * 32 * DIMK);
        const char* bsrc = (const char*)g_ws[c];
#pragma unroll
        for (int j = 0; j < 2; j++)
            cpa16(sb + 32768 + j * 8192 + tid * 16, bsrc + j * 8192 + tid * 16);
        asm volatile("cp.async.commit_group;" ::: "memory");
    };

    auto compute = [&](int stage) {
        const char* Ab = smc + stage * STG_SZ;
        const unsigned Bb = smb + stage * STG_SZ + 32768 + browoff;
#pragma unroll
        for (int kb = 0; kb < 4; kb++) {
            const unsigned ko = ((unsigned)kb * 32 + klane) ^ xorv;
            unsigned b0s0[4], b1s0[4], b0s1[4], b1s1[4];
            ldsm4(b0s0, Bb + ko);
            ldsm4(b1s0, Bb + 2048 + ko);
            ldsm4(b0s1, Bb + 8192 + ko);
            ldsm4(b1s1, Bb + 8192 + 2048 + ko);

            unsigned A0[4], A1[4];
#pragma unroll
            for (int q = 0; q < 4; q++) {
                const int row = rowA + (q & 1) * 8;
                const unsigned u = (unsigned)(lane & 3) + (unsigned)((q >> 1) * 4)
                                 + (unsigned)(kb * 8);
                const float2 v = *(const float2*)(Ab + row * 256 + ((u ^ xorA) << 3));
                const unsigned hx = __float_as_uint(v.x);
                const unsigned hy = __float_as_uint(v.y);
                A0[q] = prmt_hi(hx, hy);
                const float rx = v.x - __uint_as_float(hx & 0xffff0000u);
                const float ry = v.y - __uint_as_float(hy & 0xffff0000u);
                A1[q] = packbf(ry, rx);
            }

            MMA(acc[0], A0, b0s0[0], b0s0[2]);
            MMA(acc[1], A0, b0s0[1], b0s0[3]);
            MMA(acc[2], A0, b1s0[0], b1s0[2]);
            MMA(acc[3], A0, b1s0[1], b1s0[3]);
            MMA(acc[0], A0, b0s1[0], b0s1[2]);
            MMA(acc[1], A0, b0s1[1], b0s1[3]);
            MMA(acc[2], A0, b1s1[0], b1s1[2]);
            MMA(acc[3], A0, b1s1[1], b1s1[3]);
            MMA(acc[0], A1, b0s0[0], b0s0[2]);
            MMA(acc[1], A1, b0s0[1], b0s0[3]);
            MMA(acc[2], A1, b1s0[0], b1s0[2]);
            MMA(acc[3], A1, b1s0[1], b1s0[3]);
        }
    };

    // prologue: fill 3 stages
    loadAB(0, 0);
    loadAB(1, 1);
    loadAB(2, 2);

    for (int c = 0; c < NCHUNK; c++) {
        asm volatile("cp.async.wait_group 2;" ::: "memory");
        __syncthreads();
        if (c + NSTG - 1 < NCHUNK) loadAB(c + NSTG - 1, (c + NSTG - 1) & (NSTG - 1));
        compute(c & (NSTG - 1));
    }
    asm volatile("cp.async.wait_group 0;" ::: "memory");
    __syncthreads();

    // ---- logits -> smem: Ls[128][68] ----
    float* Ls = (float*)smc;
    {
        const int rin = lane >> 2;
        const int cin = (lane & 3) * 2;
        const int r0i = wr * 16 + rin;
#pragma unroll
        for (int n = 0; n < 4; n++) {
            const int col = we * 32 + n * 8 + cin;
            Ls[r0i * 68 + col]           = acc[n][0];
            Ls[r0i * 68 + col + 1]       = acc[n][1];
            Ls[(r0i + 8) * 68 + col]     = acc[n][2];
            Ls[(r0i + 8) * 68 + col + 1] = acc[n][3];
        }
    }
    __syncthreads();

    // ---- per-row top-3 scan, flag near-ties ----
    const float* bias_s = (const float*)(smc + BIAS_OFF);
    if (tid < MTILE) {
        const float* lrow = &Ls[tid * 68];
        float v0 = -1e30f, v1 = -1e30f, v2 = -1e30f;
        int i0 = 0, i1 = 0;
#pragma unroll 8
        for (int e = 0; e < NEXP; e++) {
            const float v = lrow[e] + bias_s[e];
            if (v > v0)      { v2 = v1; v1 = v0; i1 = i0; v0 = v; i0 = e; }
            else if (v > v1) { v2 = v1; v1 = v; i1 = e; }
            else if (v > v2) { v2 = v; }
        }
        if ((v0 - v1 < DELTA) || (v1 - v2 < DELTA)) {
            const int slot = atomicAdd((int*)(smc + CNT_OFF), 1);
            ((int*)(smc + LIST_OFF))[slot] = tid;
        } else {
            const float t  = __expf(v1 - v0);
            const float w0 = 1.0f / (1.0f + t);
            const size_t g = rowBase + tid;
            out[2 * g]     = w0;
            out[2 * g + 1] = 1.0f - w0;
            float* oi = out + 2 * (size_t)BTOK;
            oi[2 * g]     = (float)i0;
            oi[2 * g + 1] = (float)i1;
        }
    }
    __syncthreads();

    // ---- exact fp32 rescue for flagged rows ----
    const int nf = *(const int*)(smc + CNT_OFF);
    float* P  = (float*)smc;            // [8][64]
    float* Lr = (float*)(smc + 4096);
    for (int f = 0; f < nf; f++) {
        const int rrow = ((const int*)(smc + LIST_OFF))[f];
        const float* hr = h + (rowBase + rrow) * DIMK;
        const int e = tid & 63, q = tid >> 6;   // q 0..7
        const float* wp = w + (size_t)e * DIMK + q * 512;
        const float* hp = hr + q * 512;
        float s = 0.f;
        for (int k = 0; k < 512; k += 4) {
            const float4 hv = *(const float4*)(hp + k);
            const float4 wv = *(const float4*)(wp + k);
            s += hv.x * wv.x + hv.y * wv.y + hv.z * wv.z + hv.w * wv.w;
        }
        P[q * 64 + e] = s;
        __syncthreads();
        if (tid < NEXP) {
            float acc2 = bias_s[tid];
#pragma unroll
            for (int q2 = 0; q2 < 8; q2++) acc2 += P[q2 * 64 + tid];
            Lr[tid] = acc2;
        }
        __syncthreads();
        if (tid == 0) {
            float v0 = -1e30f, v1 = -1e30f;
            int i0 = 0, i1 = 0;
            for (int e2 = 0; e2 < NEXP; e2++) {
                const float v = Lr[e2];
                if (v > v0)      { v1 = v0; i1 = i0; v0 = v; i0 = e2; }
                else if (v > v1) { v1 = v; i1 = e2; }
            }
            const float t  = __expf(v1 - v0);
            const float w0 = 1.0f / (1.0f + t);
            const size_t g = rowBase + rrow;
            out[2 * g]     = w0;
            out[2 * g + 1] = 1.0f - w0;
            float* oi = out + 2 * (size_t)BTOK;
            oi[2 * g]     = (float)i0;
            oi[2 * g + 1] = (float)i1;
        }
        __syncthreads();
    }
}

extern "C" void kernel_launch(void* const* d_in, const int* in_sizes, int n_in,
                              void* d_out, int out_size)
{
    const float* h    = (const float*)d_in[0];
    const float* w    = (const float*)d_in[1];
    const float* bias = (const float*)d_in[2];
    float* out        = (float*)d_out;

    wsplit_kernel<<<(NEXP * DIMK) / 256, 256>>>(w);

    cudaFuncSetAttribute(mome_gate_mma,
                         cudaFuncAttributeMaxDynamicSharedMemorySize, SMEM_BYTES);
    mome_gate_mma<<<BTOK / MTILE, NTHR, SMEM_BYTES>>>(h, w, bias, out);
}